// round 15
// baseline (speedup 1.0000x reference)
#include <cuda_runtime.h>
#include <math.h>
#include <stdint.h>

#define BB 2
#define NH 8
#define DH 64
#define DM 512
#define NQ 4096
#define NKK 4096
#define MROWS (BB*NQ)                       // 8192
#define ATTN_ELEMS ((size_t)NH*BB*(size_t)NQ*(size_t)NKK)   // 268435456

// scratch (device globals; no allocation allowed)
__device__ float g_q[BB*NH*NQ*DH];   // d-permuted within 8-blocks
__device__ float g_k[BB*NH*NKK*DH];  // d-permuted within 8-blocks
__device__ float g_v[BB*NH*NKK*DH];  // TRANSPOSED per head: [bh][d][n]
__device__ float g_o[MROWS*DM];
__device__ float g_l[BB*NH*NQ];
__device__ unsigned int g_unit;      // attn work-stealing counter

// ===========================================================================
// helpers
// ===========================================================================
__device__ __forceinline__ uint32_t s2u(const void* p){
    uint32_t a;
    asm("{ .reg .u64 t; cvta.to.shared.u64 t, %1; cvt.u32.u64 %0, t; }"
        : "=r"(a) : "l"(p));
    return a;
}
__device__ __forceinline__ uint32_t f2tf(float f){
    uint32_t u; asm("cvt.rna.tf32.f32 %0, %1;" : "=r"(u) : "f"(f)); return u;
}
__device__ __forceinline__ float ex2f(float x){
    float y; asm("ex2.approx.ftz.f32 %0, %1;" : "=f"(y) : "f"(x)); return y;
}
__device__ __forceinline__ void mma8(float* d, const uint32_t* a,
                                     uint32_t b0, uint32_t b1){
    asm volatile("mma.sync.aligned.m16n8k8.row.col.f32.tf32.tf32.f32 "
        "{%0,%1,%2,%3}, {%4,%5,%6,%7}, {%8,%9}, {%0,%1,%2,%3};"
        : "+f"(d[0]), "+f"(d[1]), "+f"(d[2]), "+f"(d[3])
        : "r"(a[0]), "r"(a[1]), "r"(a[2]), "r"(a[3]), "r"(b0), "r"(b1));
}
__device__ __forceinline__ void cpa16(uint32_t s, const void* g){
    asm volatile("cp.async.cg.shared.global [%0], [%1], 16;" :: "r"(s), "l"(g));
}
#define CP_COMMIT() asm volatile("cp.async.commit_group;" ::: "memory")
#define CP_WAIT(n)  asm volatile("cp.async.wait_group %0;" :: "n"(n) : "memory")

// ===========================================================================
// Merged QKV projection GEMMs: one launch, gridDim.z selects q/k/v.
// C[M,512] = A[M,512] @ W[512,512]^T + bias, k-major smem tiles.
// z=0,1 -> head-split [bh][n][d] (d permuted in 8-blocks); z=2 -> [bh][d][n].
// Block (0,0,0) thread 0 also resets the attn work-stealing counter.
// ===========================================================================
__global__ __launch_bounds__(256) void gemm_qkv(
    const float* __restrict__ q, const float* __restrict__ Wq, const float* __restrict__ bq,
    const float* __restrict__ k, const float* __restrict__ Wk, const float* __restrict__ bk,
    const float* __restrict__ v, const float* __restrict__ Wv, const float* __restrict__ bv)
{
    __shared__ float As[16][72];   // k-major: [kk][row]
    __shared__ float Ws[16][72];

    int z = blockIdx.z;
    const float *A, *W, *bias;
    float* C;
    if (z == 0)      { A = q; W = Wq; bias = bq; C = g_q; }
    else if (z == 1) { A = k; W = Wk; bias = bk; C = g_k; }
    else             { A = v; W = Wv; bias = bv; C = g_v; }

    int tx = threadIdx.x, ty = threadIdx.y;
    int t  = ty * 16 + tx;
    if (z == 0 && blockIdx.x == 0 && blockIdx.y == 0 && t == 0) g_unit = 0u;

    int i0 = blockIdx.y * 64;
    int j0 = blockIdx.x * 64;
    int lr = t >> 2;          // row 0..63
    int lk = (t & 3) * 4;     // k offset 0,4,8,12

    float acc[4][4] = {};

    for (int k0 = 0; k0 < DM; k0 += 16) {
        float4 av = *(const float4*)(A + (size_t)(i0 + lr) * DM + k0 + lk);
        float4 wv = *(const float4*)(W + (size_t)(j0 + lr) * DM + k0 + lk);
        As[lk+0][lr]=av.x; As[lk+1][lr]=av.y; As[lk+2][lr]=av.z; As[lk+3][lr]=av.w;
        Ws[lk+0][lr]=wv.x; Ws[lk+1][lr]=wv.y; Ws[lk+2][lr]=wv.z; Ws[lk+3][lr]=wv.w;
        __syncthreads();
        #pragma unroll
        for (int kk = 0; kk < 16; kk++) {
            float4 a4 = *(const float4*)&As[kk][ty * 4];
            float4 w4 = *(const float4*)&Ws[kk][tx * 4];
            float a[4] = {a4.x, a4.y, a4.z, a4.w};
            float w[4] = {w4.x, w4.y, w4.z, w4.w};
            #pragma unroll
            for (int aa = 0; aa < 4; aa++)
                #pragma unroll
                for (int cc = 0; cc < 4; cc++)
                    acc[aa][cc] += a[aa] * w[cc];
        }
        __syncthreads();
    }

    int j = j0 + tx * 4;
    float4 bv4 = *(const float4*)(bias + j);
    #pragma unroll
    for (int aa = 0; aa < 4; aa++) {
        int i = i0 + ty * 4 + aa;
        float4 r = make_float4(acc[aa][0]+bv4.x, acc[aa][1]+bv4.y,
                               acc[aa][2]+bv4.z, acc[aa][3]+bv4.w);
        if (z != 2) {
            int b = i >> 12, il = i & (NQ-1);
            int h = j >> 6,  d  = j & (DH-1);
            int dpos = (d & ~7) | ((d >> 2) & 1);
            float* cb = C + (((size_t)(b*NH + h)*NQ + il)*DH + dpos);
            cb[0] = r.x; cb[2] = r.y; cb[4] = r.z; cb[6] = r.w;
        } else {
            int b = i >> 12, il = i & (NQ-1);
            int h = j >> 6,  d  = j & (DH-1);
            float* p = C + ((size_t)(b*NH + h)*DH + d) * (size_t)NQ + il;
            p[0] = r.x; p[(size_t)NQ] = r.y;
            p[2*(size_t)NQ] = r.z; p[3*(size_t)NQ] = r.w;
        }
    }
}

// ===========================================================================
// FUSED output GEMM + attn normalize, interleaved INSIDE each block (R14).
// ===========================================================================
__global__ __launch_bounds__(256) void gemm_out_norm(
    const float* __restrict__ A, const float* __restrict__ W,
    const float* __restrict__ bias, float* __restrict__ C,
    float* __restrict__ attn)
{
    __shared__ float As[16][72];
    __shared__ float Ws[16][72];
    __shared__ float sinv[64];

    int bx = blockIdx.x;
    int tid = threadIdx.x;
    int tx = tid & 15, ty = tid >> 4;
    int i0 = (bx >> 3) * 64;
    int j0 = (bx & 7) * 64;
    int lr = tid >> 2;
    int lk = (tid & 3) * 4;

    if (tid < 64) {
        int r = bx * 64 + tid;
        int i = r & (NQ - 1);
        int hb = r >> 12;
        int h = hb >> 1, bb = hb & 1;
        sinv[tid] = 1.0f / g_l[(size_t)(bb * NH + h) * NQ + i];
    }
    __syncthreads();

    float4* abase = (float4*)attn + (size_t)bx * 65536;
    float acc[4][4] = {};
    int kt = 0;

    for (int k0 = 0; k0 < DM; k0 += 16, kt++) {
        float4 av = *(const float4*)(A + (size_t)(i0 + lr) * DM + k0 + lk);
        float4 wv = *(const float4*)(W + (size_t)(j0 + lr) * DM + k0 + lk);
        As[lk+0][lr]=av.x; As[lk+1][lr]=av.y; As[lk+2][lr]=av.z; As[lk+3][lr]=av.w;
        Ws[lk+0][lr]=wv.x; Ws[lk+1][lr]=wv.y; Ws[lk+2][lr]=wv.z; Ws[lk+3][lr]=wv.w;
        __syncthreads();
        #pragma unroll
        for (int kk = 0; kk < 16; kk++) {
            float4 a4 = *(const float4*)&As[kk][ty * 4];
            float4 w4 = *(const float4*)&Ws[kk][tx * 4];
            float a[4] = {a4.x, a4.y, a4.z, a4.w};
            float w[4] = {w4.x, w4.y, w4.z, w4.w};
            #pragma unroll
            for (int aa = 0; aa < 4; aa++)
                #pragma unroll
                for (int cc = 0; cc < 4; cc++)
                    acc[aa][cc] += a[aa] * w[cc];
        }
        // ---- interleaved norm batch: 8 independent float4 r/m/w ----
        {
            int id0 = kt * 2048 + tid;
            float4 v[8];
            #pragma unroll
            for (int u = 0; u < 8; u++)
                v[u] = __ldcs(abase + id0 + u * 256);
            #pragma unroll
            for (int u = 0; u < 8; u++) {
                float inv = sinv[(id0 + u * 256) >> 10];
                v[u].x *= inv; v[u].y *= inv; v[u].z *= inv; v[u].w *= inv;
                __stcs(abase + id0 + u * 256, v[u]);
            }
        }
        __syncthreads();
    }

    int j = j0 + tx * 4;
    float4 bv = *(const float4*)(bias + j);
    #pragma unroll
    for (int aa = 0; aa < 4; aa++) {
        int i = i0 + ty * 4 + aa;
        *(float4*)(C + (size_t)i * DM + j) = make_float4(
            acc[aa][0]+bv.x, acc[aa][1]+bv.y,
            acc[aa][2]+bv.z, acc[aa][3]+bv.w);
    }
}

// ===========================================================================
// Persistent mma.sync tf32 attention with dynamic work stealing.
// 296 CTAs x 128 threads (2 CTAs/SM); units = (bh, 64-row q-block), 1024
// total, grabbed off g_unit (reset by gemm_qkv). Body identical to R7/R12.
// ===========================================================================
#define PITCH 72                 // floats per smem row (288B)
#define TILEB (64*PITCH*4)       // 18432 B per tile buffer
#define KOFF(buf)  ((buf)*TILEB)
#define VOFF(buf)  (2*TILEB + (buf)*TILEB)
#define LSUM_F     (4*TILEB/4)           // float index
#define LINV_F     (LSUM_F + 128)
#define UNIT_F     (LINV_F + 64)
#define SM_BYTES   (4*TILEB + (128+64+16)*4)
#define NT         (NKK/64)              // 64 k-tiles
#define QSCALE     0.18033688f           // 0.125 * log2(e)
#define QROWS      64
#define NUNITS     1024u
#define ACTAS      296

__global__ __launch_bounds__(128, 2) void attn_mma(
    const unsigned char* __restrict__ mask, float* __restrict__ attn)
{
    extern __shared__ float smf[];
    uint32_t sb = s2u(smf);

    int tid  = threadIdx.x;
    int w    = tid >> 5, lane = tid & 31;
    int wm   = w >> 1,  wn = w & 1;
    int g    = lane >> 2, t = lane & 3;

    for (;;) {
        if (tid == 0)
            ((unsigned int*)smf)[UNIT_F] = atomicAdd(&g_unit, 1u);
        __syncthreads();
        unsigned int unit = ((unsigned int*)smf)[UNIT_F];
        if (unit >= NUNITS) break;

        int bh = (int)(unit & 15u);            // bh fastest -> K/V L2 sharing
        int b  = bh >> 3, h = bh & 7;
        int q0 = (int)(unit >> 4) * QROWS;

        const float* qg  = g_q + ((size_t)bh * NQ + q0) * DH;
        const float* kg  = g_k + (size_t)bh * NKK * DH;     // [n][d] (d permuted)
        const float* vtg = g_v + (size_t)bh * DH * NKK;     // [d][n]
        float* ab = attn + (size_t)(h * BB + b) * NQ * NKK;
        const unsigned char* mbase = mask + (size_t)b * NQ * NKK;

        // ---- stage Q (64 x 64) into smem, pre-scaled ----
        #pragma unroll
        for (int i = 0; i < 8; i++) {
            int idx = tid + i * 128;           // 1024 float4
            int r = idx >> 4, c4 = (idx & 15) << 2;
            float4 v = *(const float4*)(qg + (size_t)r * DH + c4);
            v.x *= QSCALE; v.y *= QSCALE; v.z *= QSCALE; v.w *= QSCALE;
            *(float4*)(smf + r * PITCH + c4) = v;
        }
        __syncthreads();

        // ---- preload Q A-fragments (tf32) via paired LDS.64 ----
        uint32_t qa[2][8][4];
        #pragma unroll
        for (int mb = 0; mb < 2; mb++) {
            int R = wm * 32 + mb * 16 + g;
            #pragma unroll
            for (int s = 0; s < 8; s++) {
                float2 lo = *(const float2*)(smf + R * PITCH + s * 8 + 2 * t);
                float2 hi = *(const float2*)(smf + (R + 8) * PITCH + s * 8 + 2 * t);
                qa[mb][s][0] = f2tf(lo.x);
                qa[mb][s][1] = f2tf(hi.x);
                qa[mb][s][2] = f2tf(lo.y);
                qa[mb][s][3] = f2tf(hi.y);
            }
        }
        __syncthreads();

        float oacc[2][8][4] = {};
        float lacc[2][2] = {};

        // ---- prologue: tile 0 (K rows + VT rows) ----
        #pragma unroll
        for (int i = 0; i < 8; i++) {
            int c = tid + i * 128;              // 1024 chunks of 16B per tensor
            int r = c >> 4, c16 = c & 15;
            cpa16(sb + KOFF(0) + (uint32_t)(r * PITCH + c16 * 4) * 4,
                  kg + (size_t)r * DH + c16 * 4);
            cpa16(sb + VOFF(0) + (uint32_t)(r * PITCH + c16 * 4) * 4,
                  vtg + (size_t)r * NKK + c16 * 4);
        }
        CP_COMMIT();

        for (int it = 0; it < NT; it++) {
            int buf = it & 1;
            CP_WAIT(0);
            __syncthreads();                    // data ready + prev buffer consumed
            if (it + 1 < NT) {
                int j0n = (it + 1) * 64, nb = buf ^ 1;
                #pragma unroll
                for (int i = 0; i < 8; i++) {
                    int c = tid + i * 128;
                    int r = c >> 4, c16 = c & 15;
                    cpa16(sb + KOFF(nb) + (uint32_t)(r * PITCH + c16 * 4) * 4,
                          kg + (size_t)(j0n + r) * DH + c16 * 4);
                    cpa16(sb + VOFF(nb) + (uint32_t)(r * PITCH + c16 * 4) * 4,
                          vtg + (size_t)r * NKK + j0n + c16 * 4);
                }
                CP_COMMIT();
            }

            const float* Ks = smf + KOFF(buf) / 4;
            const float* Vs = smf + VOFF(buf) / 4;   // [d-row][k-col]

            // ---- QK^T (paired B-frags: one LDS.64 each) ----
            float sacc[2][4][4] = {};
            #pragma unroll
            for (int s = 0; s < 8; s++) {
                #pragma unroll
                for (int j = 0; j < 4; j++) {
                    int n0 = wn * 32 + j * 8;
                    float2 kv = *(const float2*)(Ks + (n0 + g) * PITCH + s * 8 + 2 * t);
                    uint32_t b0 = __float_as_uint(kv.x);
                    uint32_t b1 = __float_as_uint(kv.y);
                    mma8(sacc[0][j], qa[0][s], b0, b1);
                    mma8(sacc[1][j], qa[1][s], b0, b1);
                }
            }

            // ---- epilogue + PV (shuffle-free, paired V B-frags) ----
            int jg0 = it * 64 + wn * 32;
            #pragma unroll
            for (int j = 0; j < 4; j++) {
                uint32_t pa[2][4];
                #pragma unroll
                for (int mb = 0; mb < 2; mb++) {
                    int r0 = q0 + wm * 32 + mb * 16 + g;
                    int colg = jg0 + j * 8 + 2 * t;
                    const unsigned char* m0 = mbase + (size_t)r0 * NKK + colg;
                    unsigned short mv0 = *(const unsigned short*)m0;
                    unsigned short mv1 = *(const unsigned short*)(m0 + 8 * NKK);
                    float* s4 = sacc[mb][j];
                    float p0 = (mv0 & 0xff) ? 0.f : ex2f(s4[0]);
                    float p1 = (mv0 >> 8)   ? 0.f : ex2f(s4[1]);
                    float p2 = (mv1 & 0xff) ? 0.f : ex2f(s4[2]);
                    float p3 = (mv1 >> 8)   ? 0.f : ex2f(s4[3]);
                    lacc[mb][0] += p0 + p1;
                    lacc[mb][1] += p2 + p3;
                    __stcs((float2*)(ab + (size_t)r0 * NKK + colg), make_float2(p0, p1));
                    __stcs((float2*)(ab + (size_t)(r0 + 8) * NKK + colg), make_float2(p2, p3));
                    pa[mb][0] = f2tf(p0);
                    pa[mb][1] = f2tf(p2);
                    pa[mb][2] = f2tf(p1);
                    pa[mb][3] = f2tf(p3);
                }
                int k0 = wn * 32 + j * 8;
                #pragma unroll
                for (int jd = 0; jd < 8; jd++) {
                    float2 vv = *(const float2*)(Vs + (jd * 8 + g) * PITCH + k0 + 2 * t);
                    uint32_t b0 = __float_as_uint(vv.x);
                    uint32_t b1 = __float_as_uint(vv.y);
                    mma8(oacc[0][jd], pa[0], b0, b1);
                    mma8(oacc[1][jd], pa[1], b0, b1);
                }
            }
        }

        // ---- rowsum reduce ----
        #pragma unroll
        for (int off = 1; off <= 2; off <<= 1) {
            #pragma unroll
            for (int mb = 0; mb < 2; mb++) {
                lacc[mb][0] += __shfl_xor_sync(0xffffffffu, lacc[mb][0], off);
                lacc[mb][1] += __shfl_xor_sync(0xffffffffu, lacc[mb][1], off);
            }
        }
        float* lsum = smf + LSUM_F;
        float* linv = smf + LINV_F;
        __syncthreads();
        if (t == 0) {
            #pragma unroll
            for (int mb = 0; mb < 2; mb++) {
                lsum[wn * 64 + wm * 32 + mb * 16 + g]     = lacc[mb][0];
                lsum[wn * 64 + wm * 32 + mb * 16 + g + 8] = lacc[mb][1];
            }
        }
        __syncthreads();
        if (tid < QROWS) {
            float tot = lsum[tid] + lsum[64 + tid];
            g_l[(size_t)bh * NQ + q0 + tid] = tot;
            linv[tid] = 1.0f / tot;
        }
        __syncthreads();

        // ---- cross-warp(n) O reduction via smem (reuse KV region) ----
        if (wn == 1) {
            #pragma unroll
            for (int mb = 0; mb < 2; mb++) {
                int r = wm * 32 + mb * 16 + g;
                #pragma unroll
                for (int jd = 0; jd < 8; jd++) {
                    *(float2*)(smf + r * PITCH + jd * 8 + 2 * t) =
                        make_float2(oacc[mb][jd][0], oacc[mb][jd][1]);
                    *(float2*)(smf + (r + 8) * PITCH + jd * 8 + 2 * t) =
                        make_float2(oacc[mb][jd][2], oacc[mb][jd][3]);
                }
            }
        }
        __syncthreads();
        if (wn == 0) {
            #pragma unroll
            for (int mb = 0; mb < 2; mb++) {
                int r = wm * 32 + mb * 16 + g;
                float i0v = linv[r], i1v = linv[r + 8];
                float* og0 = g_o + (size_t)(b * NQ + q0 + r) * DM + h * DH;
                float* og1 = og0 + 8 * DM;
                #pragma unroll
                for (int jd = 0; jd < 8; jd++) {
                    float2 e0 = *(float2*)(smf + r * PITCH + jd * 8 + 2 * t);
                    float2 e1 = *(float2*)(smf + (r + 8) * PITCH + jd * 8 + 2 * t);
                    *(float2*)(og0 + jd * 8 + 2 * t) = make_float2(
                        (oacc[mb][jd][0] + e0.x) * i0v, (oacc[mb][jd][1] + e0.y) * i0v);
                    *(float2*)(og1 + jd * 8 + 2 * t) = make_float2(
                        (oacc[mb][jd][2] + e1.x) * i1v, (oacc[mb][jd][3] + e1.y) * i1v);
                }
            }
        }
        __syncthreads();   // smem reuse barrier before next unit
    }
}

extern "C" void kernel_launch(void* const* d_in, const int* in_sizes, int n_in,
                              void* d_out, int out_size)
{
    const float* q  = (const float*)d_in[0];
    const float* k  = (const float*)d_in[1];
    const float* v  = (const float*)d_in[2];
    const unsigned char* mask = (const unsigned char*)d_in[3];
    const float* Wq = (const float*)d_in[4];
    const float* bq = (const float*)d_in[5];
    const float* Wk = (const float*)d_in[6];
    const float* bk = (const float*)d_in[7];
    const float* Wv = (const float*)d_in[8];
    const float* bv = (const float*)d_in[9];
    const float* Wo = (const float*)d_in[10];
    const float* bo = (const float*)d_in[11];

    float* outbuf = (float*)d_out;
    float* attn = outbuf;
    float* outp = outbuf + ATTN_ELEMS;

    float *go;
    cudaGetSymbolAddress((void**)&go, g_o);

    dim3 blk(16, 16);
    dim3 gqkv(DM / 64, MROWS / 64, 3);

    gemm_qkv<<<gqkv, blk>>>(q, Wq, bq, k, Wk, bk, v, Wv, bv);

    cudaFuncSetAttribute(attn_mma,
        cudaFuncAttributeMaxDynamicSharedMemorySize, SM_BYTES);
    attn_mma<<<ACTAS, 128, SM_BYTES>>>(mask, attn);

    gemm_out_norm<<<1024, 256>>>(go, Wo, bo, outp, attn);
}

// round 16
// speedup vs baseline: 1.0626x; 1.0626x over previous
#include <cuda_runtime.h>
#include <math.h>
#include <stdint.h>

#define BB 2
#define NH 8
#define DH 64
#define DM 512
#define NQ 4096
#define NKK 4096
#define MROWS (BB*NQ)                       // 8192
#define ATTN_ELEMS ((size_t)NH*BB*(size_t)NQ*(size_t)NKK)   // 268435456

// scratch (device globals; no allocation allowed)
__device__ float g_q[BB*NH*NQ*DH];   // d-permuted within 8-blocks
__device__ float g_k[BB*NH*NKK*DH];  // d-permuted within 8-blocks
__device__ float g_v[BB*NH*NKK*DH];  // TRANSPOSED per head: [bh][d][n]
__device__ float g_o[MROWS*DM];
__device__ float g_l[BB*NH*NQ];

// ===========================================================================
// helpers
// ===========================================================================
__device__ __forceinline__ uint32_t s2u(const void* p){
    uint32_t a;
    asm("{ .reg .u64 t; cvta.to.shared.u64 t, %1; cvt.u32.u64 %0, t; }"
        : "=r"(a) : "l"(p));
    return a;
}
__device__ __forceinline__ uint32_t f2tf(float f){
    uint32_t u; asm("cvt.rna.tf32.f32 %0, %1;" : "=r"(u) : "f"(f)); return u;
}
__device__ __forceinline__ float ex2f(float x){
    float y; asm("ex2.approx.ftz.f32 %0, %1;" : "=f"(y) : "f"(x)); return y;
}
__device__ __forceinline__ void mma8(float* d, const uint32_t* a,
                                     uint32_t b0, uint32_t b1){
    asm volatile("mma.sync.aligned.m16n8k8.row.col.f32.tf32.tf32.f32 "
        "{%0,%1,%2,%3}, {%4,%5,%6,%7}, {%8,%9}, {%0,%1,%2,%3};"
        : "+f"(d[0]), "+f"(d[1]), "+f"(d[2]), "+f"(d[3])
        : "r"(a[0]), "r"(a[1]), "r"(a[2]), "r"(a[3]), "r"(b0), "r"(b1));
}
__device__ __forceinline__ void cpa16(uint32_t s, const void* g){
    asm volatile("cp.async.cg.shared.global [%0], [%1], 16;" :: "r"(s), "l"(g));
}
#define CP_COMMIT() asm volatile("cp.async.commit_group;" ::: "memory")
#define CP_WAIT(n)  asm volatile("cp.async.wait_group %0;" :: "n"(n) : "memory")

// ===========================================================================
// Merged QKV projection GEMMs: one launch, gridDim.z selects q/k/v.
// C[M,512] = A[M,512] @ W[512,512]^T + bias, k-major smem tiles.
// z=0,1 -> head-split [bh][n][d] (d permuted in 8-blocks); z=2 -> [bh][d][n].
// ===========================================================================
__global__ __launch_bounds__(256) void gemm_qkv(
    const float* __restrict__ q, const float* __restrict__ Wq, const float* __restrict__ bq,
    const float* __restrict__ k, const float* __restrict__ Wk, const float* __restrict__ bk,
    const float* __restrict__ v, const float* __restrict__ Wv, const float* __restrict__ bv)
{
    __shared__ float As[16][72];   // k-major: [kk][row]
    __shared__ float Ws[16][72];

    int z = blockIdx.z;
    const float *A, *W, *bias;
    float* C;
    if (z == 0)      { A = q; W = Wq; bias = bq; C = g_q; }
    else if (z == 1) { A = k; W = Wk; bias = bk; C = g_k; }
    else             { A = v; W = Wv; bias = bv; C = g_v; }

    int tx = threadIdx.x, ty = threadIdx.y;
    int t  = ty * 16 + tx;

    int i0 = blockIdx.y * 64;
    int j0 = blockIdx.x * 64;
    int lr = t >> 2;          // row 0..63
    int lk = (t & 3) * 4;     // k offset 0,4,8,12

    float acc[4][4] = {};

    for (int k0 = 0; k0 < DM; k0 += 16) {
        float4 av = *(const float4*)(A + (size_t)(i0 + lr) * DM + k0 + lk);
        float4 wv = *(const float4*)(W + (size_t)(j0 + lr) * DM + k0 + lk);
        As[lk+0][lr]=av.x; As[lk+1][lr]=av.y; As[lk+2][lr]=av.z; As[lk+3][lr]=av.w;
        Ws[lk+0][lr]=wv.x; Ws[lk+1][lr]=wv.y; Ws[lk+2][lr]=wv.z; Ws[lk+3][lr]=wv.w;
        __syncthreads();
        #pragma unroll
        for (int kk = 0; kk < 16; kk++) {
            float4 a4 = *(const float4*)&As[kk][ty * 4];
            float4 w4 = *(const float4*)&Ws[kk][tx * 4];
            float a[4] = {a4.x, a4.y, a4.z, a4.w};
            float w[4] = {w4.x, w4.y, w4.z, w4.w};
            #pragma unroll
            for (int aa = 0; aa < 4; aa++)
                #pragma unroll
                for (int cc = 0; cc < 4; cc++)
                    acc[aa][cc] += a[aa] * w[cc];
        }
        __syncthreads();
    }

    int j = j0 + tx * 4;
    float4 bv4 = *(const float4*)(bias + j);
    #pragma unroll
    for (int aa = 0; aa < 4; aa++) {
        int i = i0 + ty * 4 + aa;
        float4 r = make_float4(acc[aa][0]+bv4.x, acc[aa][1]+bv4.y,
                               acc[aa][2]+bv4.z, acc[aa][3]+bv4.w);
        if (z != 2) {
            int b = i >> 12, il = i & (NQ-1);
            int h = j >> 6,  d  = j & (DH-1);
            int dpos = (d & ~7) | ((d >> 2) & 1);
            float* cb = C + (((size_t)(b*NH + h)*NQ + il)*DH + dpos);
            cb[0] = r.x; cb[2] = r.y; cb[4] = r.z; cb[6] = r.w;
        } else {
            int b = i >> 12, il = i & (NQ-1);
            int h = j >> 6,  d  = j & (DH-1);
            float* p = C + ((size_t)(b*NH + h)*DH + d) * (size_t)NQ + il;
            p[0] = r.x; p[(size_t)NQ] = r.y;
            p[2*(size_t)NQ] = r.z; p[3*(size_t)NQ] = r.w;
        }
    }
}

// ===========================================================================
// FUSED output GEMM + attn normalize, interleaved INSIDE each block (R14).
// ===========================================================================
__global__ __launch_bounds__(256) void gemm_out_norm(
    const float* __restrict__ A, const float* __restrict__ W,
    const float* __restrict__ bias, float* __restrict__ C,
    float* __restrict__ attn)
{
    __shared__ float As[16][72];
    __shared__ float Ws[16][72];
    __shared__ float sinv[64];

    int bx = blockIdx.x;
    int tid = threadIdx.x;
    int tx = tid & 15, ty = tid >> 4;
    int i0 = (bx >> 3) * 64;
    int j0 = (bx & 7) * 64;
    int lr = tid >> 2;
    int lk = (tid & 3) * 4;

    if (tid < 64) {
        int r = bx * 64 + tid;
        int i = r & (NQ - 1);
        int hb = r >> 12;
        int h = hb >> 1, bb = hb & 1;
        sinv[tid] = 1.0f / g_l[(size_t)(bb * NH + h) * NQ + i];
    }
    __syncthreads();

    float4* abase = (float4*)attn + (size_t)bx * 65536;
    float acc[4][4] = {};
    int kt = 0;

    for (int k0 = 0; k0 < DM; k0 += 16, kt++) {
        float4 av = *(const float4*)(A + (size_t)(i0 + lr) * DM + k0 + lk);
        float4 wv = *(const float4*)(W + (size_t)(j0 + lr) * DM + k0 + lk);
        As[lk+0][lr]=av.x; As[lk+1][lr]=av.y; As[lk+2][lr]=av.z; As[lk+3][lr]=av.w;
        Ws[lk+0][lr]=wv.x; Ws[lk+1][lr]=wv.y; Ws[lk+2][lr]=wv.z; Ws[lk+3][lr]=wv.w;
        __syncthreads();
        #pragma unroll
        for (int kk = 0; kk < 16; kk++) {
            float4 a4 = *(const float4*)&As[kk][ty * 4];
            float4 w4 = *(const float4*)&Ws[kk][tx * 4];
            float a[4] = {a4.x, a4.y, a4.z, a4.w};
            float w[4] = {w4.x, w4.y, w4.z, w4.w};
            #pragma unroll
            for (int aa = 0; aa < 4; aa++)
                #pragma unroll
                for (int cc = 0; cc < 4; cc++)
                    acc[aa][cc] += a[aa] * w[cc];
        }
        // ---- interleaved norm batch: 8 independent float4 r/m/w ----
        {
            int id0 = kt * 2048 + tid;
            float4 v[8];
            #pragma unroll
            for (int u = 0; u < 8; u++)
                v[u] = __ldcs(abase + id0 + u * 256);
            #pragma unroll
            for (int u = 0; u < 8; u++) {
                float inv = sinv[(id0 + u * 256) >> 10];
                v[u].x *= inv; v[u].y *= inv; v[u].z *= inv; v[u].w *= inv;
                __stcs(abase + id0 + u * 256, v[u]);
            }
        }
        __syncthreads();
    }

    int j = j0 + tx * 4;
    float4 bv = *(const float4*)(bias + j);
    #pragma unroll
    for (int aa = 0; aa < 4; aa++) {
        int i = i0 + ty * 4 + aa;
        *(float4*)(C + (size_t)i * DM + j) = make_float4(
            acc[aa][0]+bv.x, acc[aa][1]+bv.y,
            acc[aa][2]+bv.z, acc[aa][3]+bv.w);
    }
}

// ===========================================================================
// mma.sync tf32 attention (exact R14 grid-launched state — best known).
// 128 threads / 4 warps (2m x 2n), 64 q-rows per CTA, 2 CTAs per SM.
// Warp tile 32q x 32n. Shuffle-free PV via k-permutation; LDS.64-paired
// fragments; P = ex2(S) with Q pre-scaled by 0.125*log2(e) and RNA tf32
// cvt on P A-frags; unnormalized P streamed to gmem; norm fused elsewhere.
// ===========================================================================
#define PITCH 72                 // floats per smem row (288B)
#define TILEB (64*PITCH*4)       // 18432 B per tile buffer
#define KOFF(buf)  ((buf)*TILEB)
#define VOFF(buf)  (2*TILEB + (buf)*TILEB)
#define LSUM_F     (4*TILEB/4)           // float index
#define LINV_F     (LSUM_F + 128)
#define SM_BYTES   (4*TILEB + (128+64)*4)
#define NT         (NKK/64)              // 64 k-tiles
#define QSCALE     0.18033688f           // 0.125 * log2(e)
#define QROWS      64

__global__ __launch_bounds__(128, 2) void attn_mma(
    const unsigned char* __restrict__ mask, float* __restrict__ attn)
{
    extern __shared__ float smf[];
    uint32_t sb = s2u(smf);

    int tid  = threadIdx.x;
    int w    = tid >> 5, lane = tid & 31;
    int wm   = w >> 1,  wn = w & 1;
    int g    = lane >> 2, t = lane & 3;

    int bh = blockIdx.x;               // bh fastest -> K/V L2 sharing
    int b  = bh >> 3, h = bh & 7;
    int q0 = blockIdx.y * QROWS;

    const float* qg  = g_q + ((size_t)bh * NQ + q0) * DH;
    const float* kg  = g_k + (size_t)bh * NKK * DH;     // [n][d] (d permuted)
    const float* vtg = g_v + (size_t)bh * DH * NKK;     // [d][n]
    float* ab = attn + (size_t)(h * BB + b) * NQ * NKK;
    const unsigned char* mbase = mask + (size_t)b * NQ * NKK;

    // ---- stage Q (64 x 64) into smem, pre-scaled ----
    #pragma unroll
    for (int i = 0; i < 8; i++) {
        int idx = tid + i * 128;           // 1024 float4
        int r = idx >> 4, c4 = (idx & 15) << 2;
        float4 v = *(const float4*)(qg + (size_t)r * DH + c4);
        v.x *= QSCALE; v.y *= QSCALE; v.z *= QSCALE; v.w *= QSCALE;
        *(float4*)(smf + r * PITCH + c4) = v;
    }
    __syncthreads();

    // ---- preload Q A-fragments (tf32) via paired LDS.64 ----
    uint32_t qa[2][8][4];
    #pragma unroll
    for (int mb = 0; mb < 2; mb++) {
        int R = wm * 32 + mb * 16 + g;
        #pragma unroll
        for (int s = 0; s < 8; s++) {
            float2 lo = *(const float2*)(smf + R * PITCH + s * 8 + 2 * t);
            float2 hi = *(const float2*)(smf + (R + 8) * PITCH + s * 8 + 2 * t);
            qa[mb][s][0] = f2tf(lo.x);
            qa[mb][s][1] = f2tf(hi.x);
            qa[mb][s][2] = f2tf(lo.y);
            qa[mb][s][3] = f2tf(hi.y);
        }
    }
    __syncthreads();

    float oacc[2][8][4] = {};
    float lacc[2][2] = {};

    // ---- prologue: tile 0 (K rows + VT rows) ----
    #pragma unroll
    for (int i = 0; i < 8; i++) {
        int c = tid + i * 128;              // 1024 chunks of 16B per tensor
        int r = c >> 4, c16 = c & 15;
        cpa16(sb + KOFF(0) + (uint32_t)(r * PITCH + c16 * 4) * 4,
              kg + (size_t)r * DH + c16 * 4);
        cpa16(sb + VOFF(0) + (uint32_t)(r * PITCH + c16 * 4) * 4,
              vtg + (size_t)r * NKK + c16 * 4);
    }
    CP_COMMIT();

    for (int it = 0; it < NT; it++) {
        int buf = it & 1;
        CP_WAIT(0);
        __syncthreads();                    // data ready + prev buffer consumed
        if (it + 1 < NT) {
            int j0n = (it + 1) * 64, nb = buf ^ 1;
            #pragma unroll
            for (int i = 0; i < 8; i++) {
                int c = tid + i * 128;
                int r = c >> 4, c16 = c & 15;
                cpa16(sb + KOFF(nb) + (uint32_t)(r * PITCH + c16 * 4) * 4,
                      kg + (size_t)(j0n + r) * DH + c16 * 4);
                cpa16(sb + VOFF(nb) + (uint32_t)(r * PITCH + c16 * 4) * 4,
                      vtg + (size_t)r * NKK + j0n + c16 * 4);
            }
            CP_COMMIT();
        }

        const float* Ks = smf + KOFF(buf) / 4;
        const float* Vs = smf + VOFF(buf) / 4;   // [d-row][k-col]

        // ---- QK^T (paired B-frags: one LDS.64 each) ----
        float sacc[2][4][4] = {};
        #pragma unroll
        for (int s = 0; s < 8; s++) {
            #pragma unroll
            for (int j = 0; j < 4; j++) {
                int n0 = wn * 32 + j * 8;
                float2 kv = *(const float2*)(Ks + (n0 + g) * PITCH + s * 8 + 2 * t);
                uint32_t b0 = __float_as_uint(kv.x);
                uint32_t b1 = __float_as_uint(kv.y);
                mma8(sacc[0][j], qa[0][s], b0, b1);
                mma8(sacc[1][j], qa[1][s], b0, b1);
            }
        }

        // ---- epilogue + PV (shuffle-free, paired V B-frags) ----
        int jg0 = it * 64 + wn * 32;
        #pragma unroll
        for (int j = 0; j < 4; j++) {
            uint32_t pa[2][4];
            #pragma unroll
            for (int mb = 0; mb < 2; mb++) {
                int r0 = q0 + wm * 32 + mb * 16 + g;
                int colg = jg0 + j * 8 + 2 * t;
                const unsigned char* m0 = mbase + (size_t)r0 * NKK + colg;
                unsigned short mv0 = *(const unsigned short*)m0;
                unsigned short mv1 = *(const unsigned short*)(m0 + 8 * NKK);
                float* s4 = sacc[mb][j];
                float p0 = (mv0 & 0xff) ? 0.f : ex2f(s4[0]);
                float p1 = (mv0 >> 8)   ? 0.f : ex2f(s4[1]);
                float p2 = (mv1 & 0xff) ? 0.f : ex2f(s4[2]);
                float p3 = (mv1 >> 8)   ? 0.f : ex2f(s4[3]);
                lacc[mb][0] += p0 + p1;
                lacc[mb][1] += p2 + p3;
                __stcs((float2*)(ab + (size_t)r0 * NKK + colg), make_float2(p0, p1));
                __stcs((float2*)(ab + (size_t)(r0 + 8) * NKK + colg), make_float2(p2, p3));
                pa[mb][0] = f2tf(p0);
                pa[mb][1] = f2tf(p2);
                pa[mb][2] = f2tf(p1);
                pa[mb][3] = f2tf(p3);
            }
            int k0 = wn * 32 + j * 8;
            #pragma unroll
            for (int jd = 0; jd < 8; jd++) {
                float2 vv = *(const float2*)(Vs + (jd * 8 + g) * PITCH + k0 + 2 * t);
                uint32_t b0 = __float_as_uint(vv.x);
                uint32_t b1 = __float_as_uint(vv.y);
                mma8(oacc[0][jd], pa[0], b0, b1);
                mma8(oacc[1][jd], pa[1], b0, b1);
            }
        }
    }

    // ---- rowsum reduce ----
    #pragma unroll
    for (int off = 1; off <= 2; off <<= 1) {
        #pragma unroll
        for (int mb = 0; mb < 2; mb++) {
            lacc[mb][0] += __shfl_xor_sync(0xffffffffu, lacc[mb][0], off);
            lacc[mb][1] += __shfl_xor_sync(0xffffffffu, lacc[mb][1], off);
        }
    }
    float* lsum = smf + LSUM_F;
    float* linv = smf + LINV_F;
    __syncthreads();
    if (t == 0) {
        #pragma unroll
        for (int mb = 0; mb < 2; mb++) {
            lsum[wn * 64 + wm * 32 + mb * 16 + g]     = lacc[mb][0];
            lsum[wn * 64 + wm * 32 + mb * 16 + g + 8] = lacc[mb][1];
        }
    }
    __syncthreads();
    if (tid < QROWS) {
        float tot = lsum[tid] + lsum[64 + tid];
        g_l[(size_t)bh * NQ + q0 + tid] = tot;
        linv[tid] = 1.0f / tot;
    }
    __syncthreads();

    // ---- cross-warp(n) O reduction via smem (reuse KV region) ----
    if (wn == 1) {
        #pragma unroll
        for (int mb = 0; mb < 2; mb++) {
            int r = wm * 32 + mb * 16 + g;
            #pragma unroll
            for (int jd = 0; jd < 8; jd++) {
                *(float2*)(smf + r * PITCH + jd * 8 + 2 * t) =
                    make_float2(oacc[mb][jd][0], oacc[mb][jd][1]);
                *(float2*)(smf + (r + 8) * PITCH + jd * 8 + 2 * t) =
                    make_float2(oacc[mb][jd][2], oacc[mb][jd][3]);
            }
        }
    }
    __syncthreads();
    if (wn == 0) {
        #pragma unroll
        for (int mb = 0; mb < 2; mb++) {
            int r = wm * 32 + mb * 16 + g;
            float i0v = linv[r], i1v = linv[r + 8];
            float* og0 = g_o + (size_t)(b * NQ + q0 + r) * DM + h * DH;
            float* og1 = og0 + 8 * DM;
            #pragma unroll
            for (int jd = 0; jd < 8; jd++) {
                float2 e0 = *(float2*)(smf + r * PITCH + jd * 8 + 2 * t);
                float2 e1 = *(float2*)(smf + (r + 8) * PITCH + jd * 8 + 2 * t);
                *(float2*)(og0 + jd * 8 + 2 * t) = make_float2(
                    (oacc[mb][jd][0] + e0.x) * i0v, (oacc[mb][jd][1] + e0.y) * i0v);
                *(float2*)(og1 + jd * 8 + 2 * t) = make_float2(
                    (oacc[mb][jd][2] + e1.x) * i1v, (oacc[mb][jd][3] + e1.y) * i1v);
            }
        }
    }
}

extern "C" void kernel_launch(void* const* d_in, const int* in_sizes, int n_in,
                              void* d_out, int out_size)
{
    const float* q  = (const float*)d_in[0];
    const float* k  = (const float*)d_in[1];
    const float* v  = (const float*)d_in[2];
    const unsigned char* mask = (const unsigned char*)d_in[3];
    const float* Wq = (const float*)d_in[4];
    const float* bq = (const float*)d_in[5];
    const float* Wk = (const float*)d_in[6];
    const float* bk = (const float*)d_in[7];
    const float* Wv = (const float*)d_in[8];
    const float* bv = (const float*)d_in[9];
    const float* Wo = (const float*)d_in[10];
    const float* bo = (const float*)d_in[11];

    float* outbuf = (float*)d_out;
    float* attn = outbuf;
    float* outp = outbuf + ATTN_ELEMS;

    float *go;
    cudaGetSymbolAddress((void**)&go, g_o);

    dim3 blk(16, 16);
    dim3 gqkv(DM / 64, MROWS / 64, 3);

    gemm_qkv<<<gqkv, blk>>>(q, Wq, bq, k, Wk, bk, v, Wv, bv);

    cudaFuncSetAttribute(attn_mma,
        cudaFuncAttributeMaxDynamicSharedMemorySize, SM_BYTES);
    attn_mma<<<dim3(BB * NH, NQ / QROWS), 128, SM_BYTES>>>(mask, attn);

    gemm_out_norm<<<1024, 256>>>(go, Wo, bo, outp, attn);
}

// round 17
// speedup vs baseline: 1.1210x; 1.0549x over previous
#include <cuda_runtime.h>
#include <math.h>
#include <stdint.h>

#define BB 2
#define NH 8
#define DH 64
#define DM 512
#define NQ 4096
#define NKK 4096
#define MROWS (BB*NQ)                       // 8192
#define ATTN_ELEMS ((size_t)NH*BB*(size_t)NQ*(size_t)NKK)   // 268435456

// scratch (device globals; no allocation allowed)
__device__ float g_q[BB*NH*NQ*DH];   // d-permuted within 8-blocks
__device__ float g_k[BB*NH*NKK*DH];  // d-permuted within 8-blocks
__device__ float g_v[BB*NH*NKK*DH];  // TRANSPOSED per head: [bh][d][n]
__device__ float g_o[MROWS*DM];
__device__ float g_l[BB*NH*NQ];

// ===========================================================================
// helpers
// ===========================================================================
__device__ __forceinline__ uint32_t s2u(const void* p){
    uint32_t a;
    asm("{ .reg .u64 t; cvta.to.shared.u64 t, %1; cvt.u32.u64 %0, t; }"
        : "=r"(a) : "l"(p));
    return a;
}
__device__ __forceinline__ uint32_t f2tf(float f){
    uint32_t u; asm("cvt.rna.tf32.f32 %0, %1;" : "=r"(u) : "f"(f)); return u;
}
__device__ __forceinline__ float ex2f(float x){
    float y; asm("ex2.approx.ftz.f32 %0, %1;" : "=f"(y) : "f"(x)); return y;
}
__device__ __forceinline__ void mma8(float* d, const uint32_t* a,
                                     uint32_t b0, uint32_t b1){
    asm volatile("mma.sync.aligned.m16n8k8.row.col.f32.tf32.tf32.f32 "
        "{%0,%1,%2,%3}, {%4,%5,%6,%7}, {%8,%9}, {%0,%1,%2,%3};"
        : "+f"(d[0]), "+f"(d[1]), "+f"(d[2]), "+f"(d[3])
        : "r"(a[0]), "r"(a[1]), "r"(a[2]), "r"(a[3]), "r"(b0), "r"(b1));
}
__device__ __forceinline__ void cpa16(uint32_t s, const void* g){
    asm volatile("cp.async.cg.shared.global [%0], [%1], 16;" :: "r"(s), "l"(g));
}
#define CP_COMMIT() asm volatile("cp.async.commit_group;" ::: "memory")
#define CP_WAIT(n)  asm volatile("cp.async.wait_group %0;" :: "n"(n) : "memory")

// ===========================================================================
// Merged QKV projection GEMMs, 128x128 block tile / 8x8 thread tile.
// Per kk: 4 LDS.128 feed 64 FFMA -> FFMA-bound (was LDS-crossbar-bound).
// Thread tile split as rows {ty*4..+3, 64+ty*4..+3} x cols {tx*4..+3,
// 64+tx*4..+3} so all LDS.128 are bank-conflict-free.
// z=0,1 -> head-split [bh][n][d] (d permuted in 8-blocks); z=2 -> [bh][d][n].
// ===========================================================================
#define GQ_PITCH 136

__global__ __launch_bounds__(256) void gemm_qkv(
    const float* __restrict__ q, const float* __restrict__ Wq, const float* __restrict__ bq,
    const float* __restrict__ k, const float* __restrict__ Wk, const float* __restrict__ bk,
    const float* __restrict__ v, const float* __restrict__ Wv, const float* __restrict__ bv)
{
    __shared__ float As[16][GQ_PITCH];   // k-major: [kk][row 0..127]
    __shared__ float Ws[16][GQ_PITCH];

    int z = blockIdx.z;
    const float *A, *W, *bias;
    float* C;
    if (z == 0)      { A = q; W = Wq; bias = bq; C = g_q; }
    else if (z == 1) { A = k; W = Wk; bias = bk; C = g_k; }
    else             { A = v; W = Wv; bias = bv; C = g_v; }

    int tid = threadIdx.x;
    int tx = tid & 15, ty = tid >> 4;
    int i0 = blockIdx.y * 128;
    int j0 = blockIdx.x * 128;
    int lr = tid >> 2;          // 0..63 (rows lr and lr+64)
    int lk = (tid & 3) * 4;     // 0,4,8,12

    float acc[8][8] = {};

    for (int k0 = 0; k0 < DM; k0 += 16) {
        float4 a0 = *(const float4*)(A + (size_t)(i0 + lr) * DM + k0 + lk);
        float4 a1 = *(const float4*)(A + (size_t)(i0 + lr + 64) * DM + k0 + lk);
        float4 w0 = *(const float4*)(W + (size_t)(j0 + lr) * DM + k0 + lk);
        float4 w1 = *(const float4*)(W + (size_t)(j0 + lr + 64) * DM + k0 + lk);
        As[lk+0][lr]=a0.x; As[lk+1][lr]=a0.y; As[lk+2][lr]=a0.z; As[lk+3][lr]=a0.w;
        As[lk+0][lr+64]=a1.x; As[lk+1][lr+64]=a1.y; As[lk+2][lr+64]=a1.z; As[lk+3][lr+64]=a1.w;
        Ws[lk+0][lr]=w0.x; Ws[lk+1][lr]=w0.y; Ws[lk+2][lr]=w0.z; Ws[lk+3][lr]=w0.w;
        Ws[lk+0][lr+64]=w1.x; Ws[lk+1][lr+64]=w1.y; Ws[lk+2][lr+64]=w1.z; Ws[lk+3][lr+64]=w1.w;
        __syncthreads();
        #pragma unroll
        for (int kk = 0; kk < 16; kk++) {
            float4 av0 = *(const float4*)&As[kk][ty * 4];
            float4 av1 = *(const float4*)&As[kk][64 + ty * 4];
            float4 wv0 = *(const float4*)&Ws[kk][tx * 4];
            float4 wv1 = *(const float4*)&Ws[kk][64 + tx * 4];
            float a[8] = {av0.x, av0.y, av0.z, av0.w, av1.x, av1.y, av1.z, av1.w};
            float w[8] = {wv0.x, wv0.y, wv0.z, wv0.w, wv1.x, wv1.y, wv1.z, wv1.w};
            #pragma unroll
            for (int aa = 0; aa < 8; aa++)
                #pragma unroll
                for (int cc = 0; cc < 8; cc++)
                    acc[aa][cc] += a[aa] * w[cc];
        }
        __syncthreads();
    }

    // ---- epilogue: bias + split stores ----
    #pragma unroll
    for (int aa = 0; aa < 8; aa++) {
        int i = i0 + ((aa < 4) ? (ty * 4 + aa) : (64 + ty * 4 + aa - 4));
        int b = i >> 12, il = i & (NQ - 1);
        #pragma unroll
        for (int g2 = 0; g2 < 2; g2++) {
            int jb = j0 + g2 * 64 + tx * 4;
            #pragma unroll
            for (int c4 = 0; c4 < 4; c4++) {
                int j = jb + c4;
                float val = acc[aa][g2 * 4 + c4] + __ldg(bias + j);
                int h = j >> 6, d = j & 63;
                if (z != 2) {
                    int dpos = (d & ~7) | ((d & 3) << 1) | ((d >> 2) & 1);
                    C[(((size_t)(b * NH + h) * NQ + il) * DH) + dpos] = val;
                } else {
                    C[((size_t)(b * NH + h) * DH + d) * (size_t)NQ + il] = val;
                }
            }
        }
    }
}

// ===========================================================================
// FUSED output GEMM + attn normalize, interleaved INSIDE each block (R14).
// ===========================================================================
__global__ __launch_bounds__(256) void gemm_out_norm(
    const float* __restrict__ A, const float* __restrict__ W,
    const float* __restrict__ bias, float* __restrict__ C,
    float* __restrict__ attn)
{
    __shared__ float As[16][72];
    __shared__ float Ws[16][72];
    __shared__ float sinv[64];

    int bx = blockIdx.x;
    int tid = threadIdx.x;
    int tx = tid & 15, ty = tid >> 4;
    int i0 = (bx >> 3) * 64;
    int j0 = (bx & 7) * 64;
    int lr = tid >> 2;
    int lk = (tid & 3) * 4;

    if (tid < 64) {
        int r = bx * 64 + tid;
        int i = r & (NQ - 1);
        int hb = r >> 12;
        int h = hb >> 1, bb = hb & 1;
        sinv[tid] = 1.0f / g_l[(size_t)(bb * NH + h) * NQ + i];
    }
    __syncthreads();

    float4* abase = (float4*)attn + (size_t)bx * 65536;
    float acc[4][4] = {};
    int kt = 0;

    for (int k0 = 0; k0 < DM; k0 += 16, kt++) {
        float4 av = *(const float4*)(A + (size_t)(i0 + lr) * DM + k0 + lk);
        float4 wv = *(const float4*)(W + (size_t)(j0 + lr) * DM + k0 + lk);
        As[lk+0][lr]=av.x; As[lk+1][lr]=av.y; As[lk+2][lr]=av.z; As[lk+3][lr]=av.w;
        Ws[lk+0][lr]=wv.x; Ws[lk+1][lr]=wv.y; Ws[lk+2][lr]=wv.z; Ws[lk+3][lr]=wv.w;
        __syncthreads();
        #pragma unroll
        for (int kk = 0; kk < 16; kk++) {
            float4 a4 = *(const float4*)&As[kk][ty * 4];
            float4 w4 = *(const float4*)&Ws[kk][tx * 4];
            float a[4] = {a4.x, a4.y, a4.z, a4.w};
            float w[4] = {w4.x, w4.y, w4.z, w4.w};
            #pragma unroll
            for (int aa = 0; aa < 4; aa++)
                #pragma unroll
                for (int cc = 0; cc < 4; cc++)
                    acc[aa][cc] += a[aa] * w[cc];
        }
        // ---- interleaved norm batch: 8 independent float4 r/m/w ----
        {
            int id0 = kt * 2048 + tid;
            float4 v[8];
            #pragma unroll
            for (int u = 0; u < 8; u++)
                v[u] = __ldcs(abase + id0 + u * 256);
            #pragma unroll
            for (int u = 0; u < 8; u++) {
                float inv = sinv[(id0 + u * 256) >> 10];
                v[u].x *= inv; v[u].y *= inv; v[u].z *= inv; v[u].w *= inv;
                __stcs(abase + id0 + u * 256, v[u]);
            }
        }
        __syncthreads();
    }

    int j = j0 + tx * 4;
    float4 bv = *(const float4*)(bias + j);
    #pragma unroll
    for (int aa = 0; aa < 4; aa++) {
        int i = i0 + ty * 4 + aa;
        *(float4*)(C + (size_t)i * DM + j) = make_float4(
            acc[aa][0]+bv.x, acc[aa][1]+bv.y,
            acc[aa][2]+bv.z, acc[aa][3]+bv.w);
    }
}

// ===========================================================================
// mma.sync tf32 attention (exact R14 grid-launched state — best known).
// ===========================================================================
#define PITCH 72                 // floats per smem row (288B)
#define TILEB (64*PITCH*4)       // 18432 B per tile buffer
#define KOFF(buf)  ((buf)*TILEB)
#define VOFF(buf)  (2*TILEB + (buf)*TILEB)
#define LSUM_F     (4*TILEB/4)           // float index
#define LINV_F     (LSUM_F + 128)
#define SM_BYTES   (4*TILEB + (128+64)*4)
#define NT         (NKK/64)              // 64 k-tiles
#define QSCALE     0.18033688f           // 0.125 * log2(e)
#define QROWS      64

__global__ __launch_bounds__(128, 2) void attn_mma(
    const unsigned char* __restrict__ mask, float* __restrict__ attn)
{
    extern __shared__ float smf[];
    uint32_t sb = s2u(smf);

    int tid  = threadIdx.x;
    int w    = tid >> 5, lane = tid & 31;
    int wm   = w >> 1,  wn = w & 1;
    int g    = lane >> 2, t = lane & 3;

    int bh = blockIdx.x;               // bh fastest -> K/V L2 sharing
    int b  = bh >> 3, h = bh & 7;
    int q0 = blockIdx.y * QROWS;

    const float* qg  = g_q + ((size_t)bh * NQ + q0) * DH;
    const float* kg  = g_k + (size_t)bh * NKK * DH;     // [n][d] (d permuted)
    const float* vtg = g_v + (size_t)bh * DH * NKK;     // [d][n]
    float* ab = attn + (size_t)(h * BB + b) * NQ * NKK;
    const unsigned char* mbase = mask + (size_t)b * NQ * NKK;

    // ---- stage Q (64 x 64) into smem, pre-scaled ----
    #pragma unroll
    for (int i = 0; i < 8; i++) {
        int idx = tid + i * 128;           // 1024 float4
        int r = idx >> 4, c4 = (idx & 15) << 2;
        float4 v = *(const float4*)(qg + (size_t)r * DH + c4);
        v.x *= QSCALE; v.y *= QSCALE; v.z *= QSCALE; v.w *= QSCALE;
        *(float4*)(smf + r * PITCH + c4) = v;
    }
    __syncthreads();

    // ---- preload Q A-fragments (tf32) via paired LDS.64 ----
    uint32_t qa[2][8][4];
    #pragma unroll
    for (int mb = 0; mb < 2; mb++) {
        int R = wm * 32 + mb * 16 + g;
        #pragma unroll
        for (int s = 0; s < 8; s++) {
            float2 lo = *(const float2*)(smf + R * PITCH + s * 8 + 2 * t);
            float2 hi = *(const float2*)(smf + (R + 8) * PITCH + s * 8 + 2 * t);
            qa[mb][s][0] = f2tf(lo.x);
            qa[mb][s][1] = f2tf(hi.x);
            qa[mb][s][2] = f2tf(lo.y);
            qa[mb][s][3] = f2tf(hi.y);
        }
    }
    __syncthreads();

    float oacc[2][8][4] = {};
    float lacc[2][2] = {};

    // ---- prologue: tile 0 (K rows + VT rows) ----
    #pragma unroll
    for (int i = 0; i < 8; i++) {
        int c = tid + i * 128;              // 1024 chunks of 16B per tensor
        int r = c >> 4, c16 = c & 15;
        cpa16(sb + KOFF(0) + (uint32_t)(r * PITCH + c16 * 4) * 4,
              kg + (size_t)r * DH + c16 * 4);
        cpa16(sb + VOFF(0) + (uint32_t)(r * PITCH + c16 * 4) * 4,
              vtg + (size_t)r * NKK + c16 * 4);
    }
    CP_COMMIT();

    for (int it = 0; it < NT; it++) {
        int buf = it & 1;
        CP_WAIT(0);
        __syncthreads();                    // data ready + prev buffer consumed
        if (it + 1 < NT) {
            int j0n = (it + 1) * 64, nb = buf ^ 1;
            #pragma unroll
            for (int i = 0; i < 8; i++) {
                int c = tid + i * 128;
                int r = c >> 4, c16 = c & 15;
                cpa16(sb + KOFF(nb) + (uint32_t)(r * PITCH + c16 * 4) * 4,
                      kg + (size_t)(j0n + r) * DH + c16 * 4);
                cpa16(sb + VOFF(nb) + (uint32_t)(r * PITCH + c16 * 4) * 4,
                      vtg + (size_t)r * NKK + j0n + c16 * 4);
            }
            CP_COMMIT();
        }

        const float* Ks = smf + KOFF(buf) / 4;
        const float* Vs = smf + VOFF(buf) / 4;   // [d-row][k-col]

        // ---- QK^T (paired B-frags: one LDS.64 each) ----
        float sacc[2][4][4] = {};
        #pragma unroll
        for (int s = 0; s < 8; s++) {
            #pragma unroll
            for (int j = 0; j < 4; j++) {
                int n0 = wn * 32 + j * 8;
                float2 kv = *(const float2*)(Ks + (n0 + g) * PITCH + s * 8 + 2 * t);
                uint32_t b0 = __float_as_uint(kv.x);
                uint32_t b1 = __float_as_uint(kv.y);
                mma8(sacc[0][j], qa[0][s], b0, b1);
                mma8(sacc[1][j], qa[1][s], b0, b1);
            }
        }

        // ---- epilogue + PV (shuffle-free, paired V B-frags) ----
        int jg0 = it * 64 + wn * 32;
        #pragma unroll
        for (int j = 0; j < 4; j++) {
            uint32_t pa[2][4];
            #pragma unroll
            for (int mb = 0; mb < 2; mb++) {
                int r0 = q0 + wm * 32 + mb * 16 + g;
                int colg = jg0 + j * 8 + 2 * t;
                const unsigned char* m0 = mbase + (size_t)r0 * NKK + colg;
                unsigned short mv0 = *(const unsigned short*)m0;
                unsigned short mv1 = *(const unsigned short*)(m0 + 8 * NKK);
                float* s4 = sacc[mb][j];
                float p0 = (mv0 & 0xff) ? 0.f : ex2f(s4[0]);
                float p1 = (mv0 >> 8)   ? 0.f : ex2f(s4[1]);
                float p2 = (mv1 & 0xff) ? 0.f : ex2f(s4[2]);
                float p3 = (mv1 >> 8)   ? 0.f : ex2f(s4[3]);
                lacc[mb][0] += p0 + p1;
                lacc[mb][1] += p2 + p3;
                __stcs((float2*)(ab + (size_t)r0 * NKK + colg), make_float2(p0, p1));
                __stcs((float2*)(ab + (size_t)(r0 + 8) * NKK + colg), make_float2(p2, p3));
                pa[mb][0] = f2tf(p0);
                pa[mb][1] = f2tf(p2);
                pa[mb][2] = f2tf(p1);
                pa[mb][3] = f2tf(p3);
            }
            int k0 = wn * 32 + j * 8;
            #pragma unroll
            for (int jd = 0; jd < 8; jd++) {
                float2 vv = *(const float2*)(Vs + (jd * 8 + g) * PITCH + k0 + 2 * t);
                uint32_t b0 = __float_as_uint(vv.x);
                uint32_t b1 = __float_as_uint(vv.y);
                mma8(oacc[0][jd], pa[0], b0, b1);
                mma8(oacc[1][jd], pa[1], b0, b1);
            }
        }
    }

    // ---- rowsum reduce ----
    #pragma unroll
    for (int off = 1; off <= 2; off <<= 1) {
        #pragma unroll
        for (int mb = 0; mb < 2; mb++) {
            lacc[mb][0] += __shfl_xor_sync(0xffffffffu, lacc[mb][0], off);
            lacc[mb][1] += __shfl_xor_sync(0xffffffffu, lacc[mb][1], off);
        }
    }
    float* lsum = smf + LSUM_F;
    float* linv = smf + LINV_F;
    __syncthreads();
    if (t == 0) {
        #pragma unroll
        for (int mb = 0; mb < 2; mb++) {
            lsum[wn * 64 + wm * 32 + mb * 16 + g]     = lacc[mb][0];
            lsum[wn * 64 + wm * 32 + mb * 16 + g + 8] = lacc[mb][1];
        }
    }
    __syncthreads();
    if (tid < QROWS) {
        float tot = lsum[tid] + lsum[64 + tid];
        g_l[(size_t)bh * NQ + q0 + tid] = tot;
        linv[tid] = 1.0f / tot;
    }
    __syncthreads();

    // ---- cross-warp(n) O reduction via smem (reuse KV region) ----
    if (wn == 1) {
        #pragma unroll
        for (int mb = 0; mb < 2; mb++) {
            int r = wm * 32 + mb * 16 + g;
            #pragma unroll
            for (int jd = 0; jd < 8; jd++) {
                *(float2*)(smf + r * PITCH + jd * 8 + 2 * t) =
                    make_float2(oacc[mb][jd][0], oacc[mb][jd][1]);
                *(float2*)(smf + (r + 8) * PITCH + jd * 8 + 2 * t) =
                    make_float2(oacc[mb][jd][2], oacc[mb][jd][3]);
            }
        }
    }
    __syncthreads();
    if (wn == 0) {
        #pragma unroll
        for (int mb = 0; mb < 2; mb++) {
            int r = wm * 32 + mb * 16 + g;
            float i0v = linv[r], i1v = linv[r + 8];
            float* og0 = g_o + (size_t)(b * NQ + q0 + r) * DM + h * DH;
            float* og1 = og0 + 8 * DM;
            #pragma unroll
            for (int jd = 0; jd < 8; jd++) {
                float2 e0 = *(float2*)(smf + r * PITCH + jd * 8 + 2 * t);
                float2 e1 = *(float2*)(smf + (r + 8) * PITCH + jd * 8 + 2 * t);
                *(float2*)(og0 + jd * 8 + 2 * t) = make_float2(
                    (oacc[mb][jd][0] + e0.x) * i0v, (oacc[mb][jd][1] + e0.y) * i0v);
                *(float2*)(og1 + jd * 8 + 2 * t) = make_float2(
                    (oacc[mb][jd][2] + e1.x) * i1v, (oacc[mb][jd][3] + e1.y) * i1v);
            }
        }
    }
}

extern "C" void kernel_launch(void* const* d_in, const int* in_sizes, int n_in,
                              void* d_out, int out_size)
{
    const float* q  = (const float*)d_in[0];
    const float* k  = (const float*)d_in[1];
    const float* v  = (const float*)d_in[2];
    const unsigned char* mask = (const unsigned char*)d_in[3];
    const float* Wq = (const float*)d_in[4];
    const float* bq = (const float*)d_in[5];
    const float* Wk = (const float*)d_in[6];
    const float* bk = (const float*)d_in[7];
    const float* Wv = (const float*)d_in[8];
    const float* bv = (const float*)d_in[9];
    const float* Wo = (const float*)d_in[10];
    const float* bo = (const float*)d_in[11];

    float* outbuf = (float*)d_out;
    float* attn = outbuf;
    float* outp = outbuf + ATTN_ELEMS;

    float *go;
    cudaGetSymbolAddress((void**)&go, g_o);

    dim3 gqkv(DM / 128, MROWS / 128, 3);

    gemm_qkv<<<gqkv, 256>>>(q, Wq, bq, k, Wk, bk, v, Wv, bv);

    cudaFuncSetAttribute(attn_mma,
        cudaFuncAttributeMaxDynamicSharedMemorySize, SM_BYTES);
    attn_mma<<<dim3(BB * NH, NQ / QROWS), 128, SM_BYTES>>>(mask, attn);

    gemm_out_norm<<<1024, 256>>>(go, Wo, bo, outp, attn);
}